// round 12
// baseline (speedup 1.0000x reference)
#include <cuda_runtime.h>
#include <math.h>

#define BB   8
#define NN   2048
#define DD   256
#define EE   16
#define HH   8
#define CAPC 256
#define NTOK (BB*NN)
#define EB   128
#define NG   8          // slot-groups per (e,b): 32 slots each

// ------------------------- device scratch (no allocs; zero-initialized) ----------
__device__ int   d_idx1[NTOK];
__device__ int   d_idx2[NTOK];
__device__ float d_g1[NTOK];
__device__ float d_g2[NTOK];
__device__ float d_probsum[BB*EE];      // zeroed at load; re-zeroed each run in k_combine
__device__ int   d_count1[BB*EE];
__device__ float d_U[EB*HH*DD];         // per-(e,b) q projected through Wkv_k
__device__ float d_py[EB*NG*HH*DD];     // per-group unnormalized partial y
__device__ float d_pm[EB*NG*HH];        // per-group softmax max
__device__ float d_ps[EB*NG*HH];        // per-group softmax sum
__device__ float d_gates[EB*DD];

__device__ __forceinline__ void l2_prefetch(const float* p) {
    asm volatile("prefetch.global.L2 [%0];" :: "l"(p));
}

// ===== K1: blocks 0..2047 gating (warp/token); blocks 2048..2175 qU + L2 prefetch =====
__global__ void __launch_bounds__(256) k_gate_qU(
    const float* __restrict__ x, const float* __restrict__ wg,
    const float* __restrict__ audio, const float* __restrict__ Wq,
    const float* __restrict__ Wkv, const float* __restrict__ Wp)
{
    __shared__ float swgT[EE*260];
    __shared__ float sprob[EE];
    __shared__ int   scnt[EE];
    __shared__ float sa[DD];
    __shared__ float sq[DD];

    int tid = threadIdx.x, lane = tid & 31, warp = tid >> 5;

    if (blockIdx.x < 2048) {
        // ---------------- gating ----------------
        if (tid < EE) { sprob[tid] = 0.f; scnt[tid] = 0; }
        for (int i = tid; i < DD*EE; i += 256)
            swgT[(i & 15)*260 + (i >> 4)] = wg[i];
        __syncthreads();

        int token = blockIdx.x * 8 + warp;      // 8 tokens/block, same b
        const float4* xr4 = (const float4*)(x + (size_t)token * DD);
        float4 xa = xr4[lane], xb = xr4[lane + 32];

        float p[EE];
#pragma unroll
        for (int e = 0; e < EE; e++) {
            const float4* w4 = (const float4*)(swgT + e*260);
            float4 wa = w4[lane], wb = w4[lane + 32];
            p[e] = xa.x*wa.x + xa.y*wa.y + xa.z*wa.z + xa.w*wa.w
                 + xb.x*wb.x + xb.y*wb.y + xb.z*wb.z + xb.w*wb.w;
        }
#pragma unroll
        for (int e = 0; e < EE; e++) {
#pragma unroll
            for (int off = 16; off > 0; off >>= 1)
                p[e] += __shfl_xor_sync(0xffffffffu, p[e], off);
        }
        float mx = p[0];
#pragma unroll
        for (int e = 1; e < EE; e++) mx = fmaxf(mx, p[e]);
        float s = 0.f;
#pragma unroll
        for (int e = 0; e < EE; e++) { p[e] = expf(p[e] - mx); s += p[e]; }
        float inv = 1.f / s;
#pragma unroll
        for (int e = 0; e < EE; e++) p[e] *= inv;
        int i1 = 0; float g1v = p[0];
#pragma unroll
        for (int e = 1; e < EE; e++) if (p[e] > g1v) { g1v = p[e]; i1 = e; }
        int i2 = (i1 == 0) ? 1 : 0; float g2v = p[i2];
#pragma unroll
        for (int e = 0; e < EE; e++)
            if (e != i1 && p[e] > g2v) { g2v = p[e]; i2 = e; }
        float denom = g1v + g2v + 1e-9f;

        if (lane == 0) {
            d_idx1[token] = i1; d_idx2[token] = i2;
            d_g1[token] = g1v / denom; d_g2[token] = g2v / denom;
            atomicAdd(&scnt[i1], 1);
        }
        if (lane < EE) atomicAdd(&sprob[lane], p[lane]);
        __syncthreads();
        if (tid < EE) {
            int b = (blockIdx.x * 8) >> 11;
            atomicAdd(&d_probsum[b*EE + tid], sprob[tid]);
            atomicAdd(&d_count1[b*EE + tid], scnt[tid]);
        }
    } else {
        // ---------------- qU for eb = blockIdx.x - 2048 ----------------
        int eb = blockIdx.x - 2048;
        int e = eb >> 3, b = eb & 7;
        if (tid < DD) sa[tid] = audio[b*DD + tid];
        __syncthreads();

        const float* Wqe = Wq + (size_t)e*DD*DD;
        {
            float a0=0.f, a1=0.f, a2=0.f, a3=0.f;
            for (int d = 0; d < DD; d += 4) {
                a0 += sa[d  ] * Wqe[(d  )*DD + tid];
                a1 += sa[d+1] * Wqe[(d+1)*DD + tid];
                a2 += sa[d+2] * Wqe[(d+2)*DD + tid];
                a3 += sa[d+3] * Wqe[(d+3)*DD + tid];
            }
            sq[tid] = a0 + a1 + a2 + a3;
        }
        __syncthreads();

        const float* Wkve = Wkv + (size_t)e*DD*2*DD;
        {
            int h = warp;                       // warp = head
            float qv = sq[h*32 + lane];
            float* Urow = d_U + ((size_t)eb*HH + h)*DD;
            for (int d = 0; d < DD; d += 4) {
                float v0 = Wkve[(size_t)(d  )*512 + h*32 + lane] * qv;
                float v1 = Wkve[(size_t)(d+1)*512 + h*32 + lane] * qv;
                float v2 = Wkve[(size_t)(d+2)*512 + h*32 + lane] * qv;
                float v3 = Wkve[(size_t)(d+3)*512 + h*32 + lane] * qv;
#pragma unroll
                for (int off = 16; off > 0; off >>= 1) {
                    v0 += __shfl_xor_sync(0xffffffffu, v0, off);
                    v1 += __shfl_xor_sync(0xffffffffu, v1, off);
                    v2 += __shfl_xor_sync(0xffffffffu, v2, off);
                    v3 += __shfl_xor_sync(0xffffffffu, v3, off);
                }
                if (lane == 0) { Urow[d]=v0; Urow[d+1]=v1; Urow[d+2]=v2; Urow[d+3]=v3; }
            }
        }

        // ---- L2 prefetch of og's cold weights: this (e,b)'s share ----
        // Wkv_v rows d = b*32 .. b*32+31 (512B each) and Wp rows j likewise (1KB each)
        {
            const float* Wpe = Wp + (size_t)e*DD*DD;
            // 256 threads, 2 lines each for Wkv_v (32 rows x 8? no: 512B = 4 lines/row -> 128 lines)
            // Wkv_v: 32 rows x 4 lines = 128 prefetches
            if (tid < 128) {
                int r = tid >> 2, l = tid & 3;
                l2_prefetch(Wkve + (size_t)(b*32 + r)*512 + 256 + l*32);
            }
            // Wp: 32 rows x 8 lines = 256 prefetches
            {
                int r = tid >> 3, l = tid & 7;
                l2_prefetch(Wpe + (size_t)(b*32 + r)*256 + l*32);
            }
        }
    }
}

// ==== K2: scan + logits + online-softmax partial + partial y ====
__global__ void __launch_bounds__(256) k_poslogy(const float* __restrict__ x) {
    __shared__ float sU[HH][DD];
    __shared__ int   s_slots[CAPC];
    __shared__ float sE[HH][32];
    __shared__ float smx[HH], ssm[HH];
    __shared__ int   swc1[8], swc2[8];
    __shared__ int   sbase1[8], sbase2[8];

    int ebg = blockIdx.x;
    int eb = ebg >> 3, grp = ebg & 7;       // 8 groups of 32 slots
    int e = eb >> 3, b = eb & 7;
    int tid = threadIdx.x, lane = tid & 31, warp = tid >> 5;

    if (tid < CAPC) s_slots[tid] = -1;
#pragma unroll
    for (int k = 0; k < 8; k++)
        ((float*)sU)[k*256 + tid] = d_U[(size_t)eb*2048 + k*256 + tid];

    // ---- ballot-based capacity scan (full, redundant per group) ----
    unsigned m1[8], m2[8];
    {
        int wc1 = 0, wc2 = 0;
#pragma unroll
        for (int r = 0; r < 8; r++) {
            int t = warp*256 + r*32 + lane;
            int v1 = d_idx1[b*NN + t];
            int v2 = d_idx2[b*NN + t];
            m1[r] = __ballot_sync(0xffffffffu, v1 == e);
            m2[r] = __ballot_sync(0xffffffffu, v2 == e);
            wc1 += __popc(m1[r]); wc2 += __popc(m2[r]);
        }
        if (lane == 0) { swc1[warp] = wc1; swc2[warp] = wc2; }
    }
    __syncthreads();
    if (tid == 0) {
        int run = 0;
        for (int w = 0; w < 8; w++) { sbase1[w] = run; run += swc1[w]; }
        int base2 = (run < CAPC) ? run : CAPC;     // m1_count capped
        for (int w = 0; w < 8; w++) { sbase2[w] = base2; base2 += swc2[w]; }
    }
    __syncthreads();
    {
        unsigned ltmask = (1u << lane) - 1u;
        int run = sbase1[warp];
#pragma unroll
        for (int r = 0; r < 8; r++) {
            unsigned m = m1[r];
            if (m & (1u << lane)) {
                int slot = run + __popc(m & ltmask);
                int t = warp*256 + r*32 + lane;
                if (slot < CAPC) s_slots[slot] = t;
                else if (grp == 0) d_g1[b*NN + t] = 0.f;
            }
            run += __popc(m);
        }
        run = sbase2[warp];
#pragma unroll
        for (int r = 0; r < 8; r++) {
            unsigned m = m2[r];
            if (m & (1u << lane)) {
                int slot = run + __popc(m & ltmask);
                int t = warp*256 + r*32 + lane;
                if (slot < CAPC) s_slots[slot] = t;
                else if (grp == 0) d_g2[b*NN + t] = 0.f;
            }
            run += __popc(m);
        }
    }
    __syncthreads();

    // ---- logits for this group's 32 slots (warp handles 4) ----
    const float scale = 0.17677669529663687f;    // 32^-0.5
#pragma unroll
    for (int ci = 0; ci < 4; ci++) {
        int sl = warp*4 + ci;                    // 0..31 within group
        int tok = s_slots[grp*32 + sl];
        float part[HH];
        if (tok >= 0) {
            const float4* xr4 = (const float4*)(x + ((size_t)b*NN + tok)*DD);
            float4 xa = xr4[lane], xb = xr4[lane + 32];
#pragma unroll
            for (int h = 0; h < HH; h++) {
                const float4* u4 = (const float4*)(&sU[h][0]);
                float4 ua = u4[lane], ub = u4[lane + 32];
                part[h] = xa.x*ua.x + xa.y*ua.y + xa.z*ua.z + xa.w*ua.w
                        + xb.x*ub.x + xb.y*ub.y + xb.z*ub.z + xb.w*ub.w;
            }
        } else {
#pragma unroll
            for (int h = 0; h < HH; h++) part[h] = 0.f;
        }
#pragma unroll
        for (int h = 0; h < HH; h++) {
            float v = part[h];
#pragma unroll
            for (int off = 16; off > 0; off >>= 1)
                v += __shfl_xor_sync(0xffffffffu, v, off);
            if (lane == 0) sE[h][sl] = (tok >= 0) ? v * scale : 0.f;
        }
    }
    __syncthreads();

    // ---- group-local online-softmax partial (warp h over 32 logits) ----
    if (warp < HH) {
        float v = sE[warp][lane];
        float mx = v;
#pragma unroll
        for (int off = 16; off > 0; off >>= 1)
            mx = fmaxf(mx, __shfl_xor_sync(0xffffffffu, mx, off));
        float ev = expf(v - mx);
        float s = ev;
#pragma unroll
        for (int off = 16; off > 0; off >>= 1)
            s += __shfl_xor_sync(0xffffffffu, s, off);
        sE[warp][lane] = ev;
        if (lane == 0) { smx[warp] = mx; ssm[warp] = s; }
    }
    __syncthreads();

    // ---- unnormalized partial y over own 32 slots (thread = d), MLP-4, x L1-hot ----
    {
        float yv[HH];
#pragma unroll
        for (int h = 0; h < HH; h++) yv[h] = 0.f;
#pragma unroll
        for (int c4 = 0; c4 < 8; c4++) {
            int t0 = s_slots[grp*32 + c4*4+0], t1 = s_slots[grp*32 + c4*4+1];
            int t2 = s_slots[grp*32 + c4*4+2], t3 = s_slots[grp*32 + c4*4+3];
            float x0 = (t0 >= 0) ? x[((size_t)b*NN + t0)*DD + tid] : 0.f;
            float x1 = (t1 >= 0) ? x[((size_t)b*NN + t1)*DD + tid] : 0.f;
            float x2 = (t2 >= 0) ? x[((size_t)b*NN + t2)*DD + tid] : 0.f;
            float x3 = (t3 >= 0) ? x[((size_t)b*NN + t3)*DD + tid] : 0.f;
#pragma unroll
            for (int h = 0; h < HH; h++) {
                yv[h] += sE[h][c4*4+0] * x0 + sE[h][c4*4+1] * x1
                       + sE[h][c4*4+2] * x2 + sE[h][c4*4+3] * x3;
            }
        }
#pragma unroll
        for (int h = 0; h < HH; h++)
            d_py[((size_t)ebg*HH + h)*DD + tid] = yv[h];
        if (tid < HH) { d_pm[ebg*HH + tid] = smx[tid]; d_ps[ebg*HH + tid] = ssm[tid]; }
    }
}

// ==== K3: softmax-merge + o-projection + sigmoid gate; 1024 thr, MLP-4 matvecs ====
__global__ void __launch_bounds__(1024, 1) k_og(
    const float* __restrict__ Wkv, const float* __restrict__ Wp,
    const float* __restrict__ bp)
{
    __shared__ float sw[NG][HH];
    __shared__ float sY[HH][DD];
    __shared__ float sO[DD];
    __shared__ float sRed[4][DD];

    int eb = blockIdx.x;
    int e = eb >> 3;
    int tid = threadIdx.x;
    int g = tid >> 8, wtid = tid & 255;

    // merge weights per head: w[g][h] = exp(m_g - M) / S
    if (tid < HH) {
        float m[NG];
#pragma unroll
        for (int g2 = 0; g2 < NG; g2++) m[g2] = d_pm[(eb*NG + g2)*HH + tid];
        float M = m[0];
#pragma unroll
        for (int g2 = 1; g2 < NG; g2++) M = fmaxf(M, m[g2]);
        float S = 0.f;
        float w[NG];
#pragma unroll
        for (int g2 = 0; g2 < NG; g2++) {
            w[g2] = expf(m[g2] - M);
            S += w[g2] * d_ps[(eb*NG + g2)*HH + tid];
        }
        float invS = 1.f / S;
#pragma unroll
        for (int g2 = 0; g2 < NG; g2++) sw[g2][tid] = w[g2] * invS;
    }
    __syncthreads();

    // sY[h][d] = sum_g w[g][h] * py[g][h][d]   (1024 threads, 2 elems each)
    for (int i = tid; i < HH*DD; i += 1024) {
        int h = i >> 8;
        float a0 = 0.f, a1 = 0.f;
#pragma unroll
        for (int g2 = 0; g2 < NG; g2 += 2) {
            a0 += d_py[(size_t)(eb*NG + g2  )*2048 + i] * sw[g2  ][h];
            a1 += d_py[(size_t)(eb*NG + g2+1)*2048 + i] * sw[g2+1][h];
        }
        ((float*)sY)[i] = a0 + a1;
    }
    __syncthreads();

    // o[j] = sum_d y[h(j)][d] * Wkv_v[e][d][256+j]; 4-way split over d, MLP-4
    const float* Wkve = Wkv + (size_t)e*DD*2*DD;
    {
        int h = wtid >> 5;
        int d0 = g*64;
        float a0=0.f, a1=0.f, a2=0.f, a3=0.f;
#pragma unroll 4
        for (int d = d0; d < d0 + 64; d += 4) {
            a0 += sY[h][d  ] * Wkve[(size_t)(d  )*512 + 256 + wtid];
            a1 += sY[h][d+1] * Wkve[(size_t)(d+1)*512 + 256 + wtid];
            a2 += sY[h][d+2] * Wkve[(size_t)(d+2)*512 + 256 + wtid];
            a3 += sY[h][d+3] * Wkve[(size_t)(d+3)*512 + 256 + wtid];
        }
        sRed[g][wtid] = a0 + a1 + a2 + a3;
    }
    __syncthreads();
    if (tid < DD)
        sO[tid] = sRed[0][tid] + sRed[1][tid] + sRed[2][tid] + sRed[3][tid];
    __syncthreads();

    // gate[d] = sigmoid(sum_j o[j]*Wp[e][j][d] + bp[e][d]); 4-way split over j, MLP-4
    {
        const float* Wpe = Wp + (size_t)e*DD*DD;
        int j0 = g*64;
        float a0=0.f, a1=0.f, a2=0.f, a3=0.f;
#pragma unroll 4
        for (int j = j0; j < j0 + 64; j += 4) {
            a0 += sO[j  ] * Wpe[(j  )*DD + wtid];
            a1 += sO[j+1] * Wpe[(j+1)*DD + wtid];
            a2 += sO[j+2] * Wpe[(j+2)*DD + wtid];
            a3 += sO[j+3] * Wpe[(j+3)*DD + wtid];
        }
        sRed[g][wtid] = a0 + a1 + a2 + a3;
    }
    __syncthreads();
    if (tid < DD) {
        float gsum = sRed[0][tid] + sRed[1][tid] + sRed[2][tid] + sRed[3][tid]
                   + bp[e*DD + tid];
        d_gates[eb*DD + tid] = 1.f / (1.f + expf(-gsum));
    }
}

// ============ K4: combine + loss (block 0) + counter reset ============
__global__ void __launch_bounds__(256) k_combine(
    const float* __restrict__ x, float* __restrict__ out, int out_size)
{
    __shared__ float red[128];
    int tid = threadIdx.x;
    int token = blockIdx.x*4 + (tid >> 6);
    int q = tid & 63;
    int b = token >> 11;
    int i1 = d_idx1[token], i2 = d_idx2[token];
    float w1 = d_g1[token], w2 = d_g2[token];
    float4 xv = ((const float4*)x)[(size_t)token*64 + q];
    float4 ga = ((const float4*)(d_gates + (i1*BB + b)*DD))[q];
    float4 gb = ((const float4*)(d_gates + (i2*BB + b)*DD))[q];
    float4 o;
    o.x = xv.x * (w1*ga.x + w2*gb.x);
    o.y = xv.y * (w1*ga.y + w2*gb.y);
    o.z = xv.z * (w1*ga.z + w2*gb.z);
    o.w = xv.w * (w1*ga.w + w2*gb.w);
    ((float4*)out)[(size_t)token*64 + q] = o;

    if (blockIdx.x == 0) {
        if (tid < 128) {
            red[tid] = d_probsum[tid] * (float)d_count1[tid];
            d_probsum[tid] = 0.f;          // reset for next (deterministic) run
            d_count1[tid] = 0;
        }
        __syncthreads();
        if (tid < 64) red[tid] += red[tid + 64];
        __syncthreads();
        if (tid < 32) {
            float v = red[tid] + red[tid + 32];
#pragma unroll
            for (int off = 16; off > 0; off >>= 1)
                v += __shfl_xor_sync(0xffffffffu, v, off);
            if (tid == 0 && out_size > NTOK*DD) {
                float coef = (float)(EE*EE) * 0.01f / ((float)NN * (float)NN * (float)(BB*EE));
                out[NTOK*DD] = v * coef;
            }
        }
    }
}

// ------------------------- launch -------------------------
extern "C" void kernel_launch(void* const* d_in, const int* in_sizes, int n_in,
                              void* d_out, int out_size) {
    const float* x     = (const float*)d_in[0];
    const float* audio = (const float*)d_in[1];
    const float* wg    = (const float*)d_in[2];
    const float* Wq    = (const float*)d_in[3];
    const float* Wkv   = (const float*)d_in[4];
    const float* Wp    = (const float*)d_in[5];
    const float* bp    = (const float*)d_in[6];
    float* out = (float*)d_out;

    k_gate_qU<<<2048 + EB, 256>>>(x, wg, audio, Wq, Wkv, Wp);
    k_poslogy<<<EB*NG, 256>>>(x);
    k_og<<<EB, 1024>>>(Wkv, Wp, bp);
    k_combine<<<NTOK/4, 256>>>(x, out, out_size);
}

// round 13
// speedup vs baseline: 1.1025x; 1.1025x over previous
#include <cuda_runtime.h>
#include <math.h>

#define BB   8
#define NN   2048
#define DD   256
#define EE   16
#define HH   8
#define CAPC 256
#define NTOK (BB*NN)
#define EB   128
#define NG   8          // slot-groups per (e,b): 32 slots each

// ------------------------- device scratch (no allocs; zero-initialized) ----------
__device__ int   d_idx1[NTOK];
__device__ int   d_idx2[NTOK];
__device__ float d_g1[NTOK];
__device__ float d_g2[NTOK];
__device__ float d_probsum[BB*EE];      // zeroed at load; re-zeroed each run in k_combine
__device__ int   d_count1[BB*EE];
__device__ float d_U[EB*HH*DD];         // per-(e,b) q projected through Wkv_k
__device__ float d_py[EB*NG*HH*DD];     // per-group unnormalized partial y
__device__ float d_pm[EB*NG*HH];        // per-group softmax max
__device__ float d_ps[EB*NG*HH];        // per-group softmax sum
__device__ float d_gates[EB*DD];

__device__ __forceinline__ void l2_prefetch(const float* p) {
    asm volatile("prefetch.global.L2 [%0];" :: "l"(p));
}

// ============ K1: gating, warp per token; wg transposed into smem ============
__global__ void __launch_bounds__(256) k_gating(
    const float* __restrict__ x, const float* __restrict__ wg)
{
    __shared__ float swgT[EE*260];
    __shared__ float sprob[EE];
    __shared__ int   scnt[EE];

    int tid = threadIdx.x, lane = tid & 31, warp = tid >> 5;
    if (tid < EE) { sprob[tid] = 0.f; scnt[tid] = 0; }
    for (int i = tid; i < DD*EE; i += 256)
        swgT[(i & 15)*260 + (i >> 4)] = wg[i];
    __syncthreads();

    int token = blockIdx.x * 8 + warp;      // 8 tokens/block, same b
    const float4* xr4 = (const float4*)(x + (size_t)token * DD);
    float4 xa = xr4[lane], xb = xr4[lane + 32];

    float p[EE];
#pragma unroll
    for (int e = 0; e < EE; e++) {
        const float4* w4 = (const float4*)(swgT + e*260);
        float4 wa = w4[lane], wb = w4[lane + 32];
        p[e] = xa.x*wa.x + xa.y*wa.y + xa.z*wa.z + xa.w*wa.w
             + xb.x*wb.x + xb.y*wb.y + xb.z*wb.z + xb.w*wb.w;
    }
#pragma unroll
    for (int e = 0; e < EE; e++) {
#pragma unroll
        for (int off = 16; off > 0; off >>= 1)
            p[e] += __shfl_xor_sync(0xffffffffu, p[e], off);
    }
    float mx = p[0];
#pragma unroll
    for (int e = 1; e < EE; e++) mx = fmaxf(mx, p[e]);
    float s = 0.f;
#pragma unroll
    for (int e = 0; e < EE; e++) { p[e] = expf(p[e] - mx); s += p[e]; }
    float inv = 1.f / s;
#pragma unroll
    for (int e = 0; e < EE; e++) p[e] *= inv;
    int i1 = 0; float g1v = p[0];
#pragma unroll
    for (int e = 1; e < EE; e++) if (p[e] > g1v) { g1v = p[e]; i1 = e; }
    int i2 = (i1 == 0) ? 1 : 0; float g2v = p[i2];
#pragma unroll
    for (int e = 0; e < EE; e++)
        if (e != i1 && p[e] > g2v) { g2v = p[e]; i2 = e; }
    float denom = g1v + g2v + 1e-9f;

    if (lane == 0) {
        d_idx1[token] = i1; d_idx2[token] = i2;
        d_g1[token] = g1v / denom; d_g2[token] = g2v / denom;
        atomicAdd(&scnt[i1], 1);
    }
    if (lane < EE) atomicAdd(&sprob[lane], p[lane]);
    __syncthreads();
    if (tid < EE) {
        int b = (blockIdx.x * 8) >> 11;
        atomicAdd(&d_probsum[b*EE + tid], sprob[tid]);
        atomicAdd(&d_count1[b*EE + tid], scnt[tid]);
    }
}

// ============ K2: qU, block per (e,b), 1024 threads, 4-way split ============
__global__ void __launch_bounds__(1024, 1) k_qU(
    const float* __restrict__ audio, const float* __restrict__ Wq,
    const float* __restrict__ Wkv)
{
    __shared__ float sa[DD];
    __shared__ float sq[DD];
    __shared__ float sRed[4][DD];

    int e = blockIdx.x >> 3;
    int b = blockIdx.x & 7;
    int tid = threadIdx.x, lane = tid & 31, warp = tid >> 5;
    int g = tid >> 8, wtid = tid & 255;

    if (tid < DD) sa[tid] = audio[b*DD + tid];
    __syncthreads();

    const float* Wqe = Wq + (size_t)e*DD*DD;
    {
        float acc = 0.f;
        int d0 = g*64;
#pragma unroll 4
        for (int d = d0; d < d0 + 64; d++) acc += sa[d] * Wqe[d*DD + wtid];
        sRed[g][wtid] = acc;
    }
    __syncthreads();
    if (tid < DD)
        sq[tid] = sRed[0][tid] + sRed[1][tid] + sRed[2][tid] + sRed[3][tid];
    __syncthreads();

    const float* Wkve = Wkv + (size_t)e*DD*2*DD;
    {
        int h = warp & 7;
        int dbase = (warp >> 3) * 64;
        float qv = sq[h*32 + lane];
        float* Urow = d_U + ((size_t)blockIdx.x*HH + h)*DD;
#pragma unroll 4
        for (int d = dbase; d < dbase + 64; d++) {
            float v = Wkve[(size_t)d*512 + h*32 + lane] * qv;
#pragma unroll
            for (int off = 16; off > 0; off >>= 1)
                v += __shfl_xor_sync(0xffffffffu, v, off);
            if (lane == 0) Urow[d] = v;
        }
    }
}

// ==== K3: scan + logits + online-softmax partial + partial y + weight prefetch ====
__global__ void __launch_bounds__(256) k_poslogy(
    const float* __restrict__ x, const float* __restrict__ Wkv,
    const float* __restrict__ Wp)
{
    __shared__ float sU[HH][DD];
    __shared__ int   s_slots[CAPC];
    __shared__ float sE[HH][32];
    __shared__ float smx[HH], ssm[HH];
    __shared__ int   swc1[8], swc2[8];
    __shared__ int   sbase1[8], sbase2[8];

    int ebg = blockIdx.x;
    int eb = ebg >> 3, grp = ebg & 7;       // 8 groups of 32 slots
    int e = eb >> 3, b = eb & 7;
    int tid = threadIdx.x, lane = tid & 31, warp = tid >> 5;

    if (tid < CAPC) s_slots[tid] = -1;
#pragma unroll
    for (int k = 0; k < 8; k++)
        ((float*)sU)[k*256 + tid] = d_U[(size_t)eb*2048 + k*256 + tid];

    // ---- L2 prefetch of og's cold weights: this block's 1/8th (e,b,grp) share ----
    // Wkv_v rows d = grp*32..grp*32+31 of expert e: 32 rows x 4 lines (last 1KB of each 2KB row)
    // Wp rows j likewise: 32 rows x 8 lines
    {
        const float* Wkve = Wkv + (size_t)e*DD*2*DD;
        const float* Wpe  = Wp  + (size_t)e*DD*DD;
        if (tid < 128) {                       // Wkv_v: 128 lines
            int r = tid >> 2, l = tid & 3;
            l2_prefetch(Wkve + (size_t)(grp*32 + r)*512 + 256 + l*32);
        }
        {                                      // Wp: 256 lines
            int r = tid >> 3, l = tid & 7;
            l2_prefetch(Wpe + (size_t)(grp*32 + r)*256 + l*32);
        }
    }

    // ---- ballot-based capacity scan (full, redundant per group) ----
    unsigned m1[8], m2[8];
    {
        int wc1 = 0, wc2 = 0;
#pragma unroll
        for (int r = 0; r < 8; r++) {
            int t = warp*256 + r*32 + lane;
            int v1 = d_idx1[b*NN + t];
            int v2 = d_idx2[b*NN + t];
            m1[r] = __ballot_sync(0xffffffffu, v1 == e);
            m2[r] = __ballot_sync(0xffffffffu, v2 == e);
            wc1 += __popc(m1[r]); wc2 += __popc(m2[r]);
        }
        if (lane == 0) { swc1[warp] = wc1; swc2[warp] = wc2; }
    }
    __syncthreads();
    if (tid == 0) {
        int run = 0;
        for (int w = 0; w < 8; w++) { sbase1[w] = run; run += swc1[w]; }
        int base2 = (run < CAPC) ? run : CAPC;     // m1_count capped
        for (int w = 0; w < 8; w++) { sbase2[w] = base2; base2 += swc2[w]; }
    }
    __syncthreads();
    {
        unsigned ltmask = (1u << lane) - 1u;
        int run = sbase1[warp];
#pragma unroll
        for (int r = 0; r < 8; r++) {
            unsigned m = m1[r];
            if (m & (1u << lane)) {
                int slot = run + __popc(m & ltmask);
                int t = warp*256 + r*32 + lane;
                if (slot < CAPC) s_slots[slot] = t;
                else if (grp == 0) d_g1[b*NN + t] = 0.f;
            }
            run += __popc(m);
        }
        run = sbase2[warp];
#pragma unroll
        for (int r = 0; r < 8; r++) {
            unsigned m = m2[r];
            if (m & (1u << lane)) {
                int slot = run + __popc(m & ltmask);
                int t = warp*256 + r*32 + lane;
                if (slot < CAPC) s_slots[slot] = t;
                else if (grp == 0) d_g2[b*NN + t] = 0.f;
            }
            run += __popc(m);
        }
    }
    __syncthreads();

    // ---- logits for this group's 32 slots (warp handles 4) ----
    const float scale = 0.17677669529663687f;    // 32^-0.5
#pragma unroll
    for (int ci = 0; ci < 4; ci++) {
        int sl = warp*4 + ci;                    // 0..31 within group
        int tok = s_slots[grp*32 + sl];
        float part[HH];
        if (tok >= 0) {
            const float4* xr4 = (const float4*)(x + ((size_t)b*NN + tok)*DD);
            float4 xa = xr4[lane], xb = xr4[lane + 32];
#pragma unroll
            for (int h = 0; h < HH; h++) {
                const float4* u4 = (const float4*)(&sU[h][0]);
                float4 ua = u4[lane], ub = u4[lane + 32];
                part[h] = xa.x*ua.x + xa.y*ua.y + xa.z*ua.z + xa.w*ua.w
                        + xb.x*ub.x + xb.y*ub.y + xb.z*ub.z + xb.w*ub.w;
            }
        } else {
#pragma unroll
            for (int h = 0; h < HH; h++) part[h] = 0.f;
        }
#pragma unroll
        for (int h = 0; h < HH; h++) {
            float v = part[h];
#pragma unroll
            for (int off = 16; off > 0; off >>= 1)
                v += __shfl_xor_sync(0xffffffffu, v, off);
            if (lane == 0) sE[h][sl] = (tok >= 0) ? v * scale : 0.f;
        }
    }
    __syncthreads();

    // ---- group-local online-softmax partial (warp h over 32 logits) ----
    if (warp < HH) {
        float v = sE[warp][lane];
        float mx = v;
#pragma unroll
        for (int off = 16; off > 0; off >>= 1)
            mx = fmaxf(mx, __shfl_xor_sync(0xffffffffu, mx, off));
        float ev = expf(v - mx);
        float s = ev;
#pragma unroll
        for (int off = 16; off > 0; off >>= 1)
            s += __shfl_xor_sync(0xffffffffu, s, off);
        sE[warp][lane] = ev;
        if (lane == 0) { smx[warp] = mx; ssm[warp] = s; }
    }
    __syncthreads();

    // ---- unnormalized partial y over own 32 slots (thread = d), MLP-4, x L1-hot ----
    {
        float yv[HH];
#pragma unroll
        for (int h = 0; h < HH; h++) yv[h] = 0.f;
#pragma unroll
        for (int c4 = 0; c4 < 8; c4++) {
            int t0 = s_slots[grp*32 + c4*4+0], t1 = s_slots[grp*32 + c4*4+1];
            int t2 = s_slots[grp*32 + c4*4+2], t3 = s_slots[grp*32 + c4*4+3];
            float x0 = (t0 >= 0) ? x[((size_t)b*NN + t0)*DD + tid] : 0.f;
            float x1 = (t1 >= 0) ? x[((size_t)b*NN + t1)*DD + tid] : 0.f;
            float x2 = (t2 >= 0) ? x[((size_t)b*NN + t2)*DD + tid] : 0.f;
            float x3 = (t3 >= 0) ? x[((size_t)b*NN + t3)*DD + tid] : 0.f;
#pragma unroll
            for (int h = 0; h < HH; h++) {
                yv[h] += sE[h][c4*4+0] * x0 + sE[h][c4*4+1] * x1
                       + sE[h][c4*4+2] * x2 + sE[h][c4*4+3] * x3;
            }
        }
#pragma unroll
        for (int h = 0; h < HH; h++)
            d_py[((size_t)ebg*HH + h)*DD + tid] = yv[h];
        if (tid < HH) { d_pm[ebg*HH + tid] = smx[tid]; d_ps[ebg*HH + tid] = ssm[tid]; }
    }
}

// ==== K4: softmax-merge + o-projection + sigmoid gate; 1024 thr, MLP-4 matvecs ====
__global__ void __launch_bounds__(1024, 1) k_og(
    const float* __restrict__ Wkv, const float* __restrict__ Wp,
    const float* __restrict__ bp)
{
    __shared__ float sw[NG][HH];
    __shared__ float sY[HH][DD];
    __shared__ float sO[DD];
    __shared__ float sRed[4][DD];

    int eb = blockIdx.x;
    int e = eb >> 3;
    int tid = threadIdx.x;
    int g = tid >> 8, wtid = tid & 255;

    // merge weights per head: w[g][h] = exp(m_g - M) / S
    if (tid < HH) {
        float m[NG];
#pragma unroll
        for (int g2 = 0; g2 < NG; g2++) m[g2] = d_pm[(eb*NG + g2)*HH + tid];
        float M = m[0];
#pragma unroll
        for (int g2 = 1; g2 < NG; g2++) M = fmaxf(M, m[g2]);
        float S = 0.f;
        float w[NG];
#pragma unroll
        for (int g2 = 0; g2 < NG; g2++) {
            w[g2] = expf(m[g2] - M);
            S += w[g2] * d_ps[(eb*NG + g2)*HH + tid];
        }
        float invS = 1.f / S;
#pragma unroll
        for (int g2 = 0; g2 < NG; g2++) sw[g2][tid] = w[g2] * invS;
    }
    __syncthreads();

    // sY[h][d] = sum_g w[g][h] * py[g][h][d]   (1024 threads, 2 elems each, MLP-2)
    for (int i = tid; i < HH*DD; i += 1024) {
        int h = i >> 8;
        float a0 = 0.f, a1 = 0.f;
#pragma unroll
        for (int g2 = 0; g2 < NG; g2 += 2) {
            a0 += d_py[(size_t)(eb*NG + g2  )*2048 + i] * sw[g2  ][h];
            a1 += d_py[(size_t)(eb*NG + g2+1)*2048 + i] * sw[g2+1][h];
        }
        ((float*)sY)[i] = a0 + a1;
    }
    __syncthreads();

    // o[j] = sum_d y[h(j)][d] * Wkv_v[e][d][256+j]; 4-way split over d, MLP-4
    const float* Wkve = Wkv + (size_t)e*DD*2*DD;
    {
        int h = wtid >> 5;
        int d0 = g*64;
        float a0=0.f, a1=0.f, a2=0.f, a3=0.f;
#pragma unroll 4
        for (int d = d0; d < d0 + 64; d += 4) {
            a0 += sY[h][d  ] * Wkve[(size_t)(d  )*512 + 256 + wtid];
            a1 += sY[h][d+1] * Wkve[(size_t)(d+1)*512 + 256 + wtid];
            a2 += sY[h][d+2] * Wkve[(size_t)(d+2)*512 + 256 + wtid];
            a3 += sY[h][d+3] * Wkve[(size_t)(d+3)*512 + 256 + wtid];
        }
        sRed[g][wtid] = a0 + a1 + a2 + a3;
    }
    __syncthreads();
    if (tid < DD)
        sO[tid] = sRed[0][tid] + sRed[1][tid] + sRed[2][tid] + sRed[3][tid];
    __syncthreads();

    // gate[d] = sigmoid(sum_j o[j]*Wp[e][j][d] + bp[e][d]); 4-way split over j, MLP-4
    {
        const float* Wpe = Wp + (size_t)e*DD*DD;
        int j0 = g*64;
        float a0=0.f, a1=0.f, a2=0.f, a3=0.f;
#pragma unroll 4
        for (int j = j0; j < j0 + 64; j += 4) {
            a0 += sO[j  ] * Wpe[(j  )*DD + wtid];
            a1 += sO[j+1] * Wpe[(j+1)*DD + wtid];
            a2 += sO[j+2] * Wpe[(j+2)*DD + wtid];
            a3 += sO[j+3] * Wpe[(j+3)*DD + wtid];
        }
        sRed[g][wtid] = a0 + a1 + a2 + a3;
    }
    __syncthreads();
    if (tid < DD) {
        float gsum = sRed[0][tid] + sRed[1][tid] + sRed[2][tid] + sRed[3][tid]
                   + bp[e*DD + tid];
        d_gates[eb*DD + tid] = 1.f / (1.f + expf(-gsum));
    }
}

// ============ K5: combine + loss (block 0) + counter reset ============
__global__ void __launch_bounds__(256) k_combine(
    const float* __restrict__ x, float* __restrict__ out, int out_size)
{
    __shared__ float red[128];
    int tid = threadIdx.x;
    int token = blockIdx.x*4 + (tid >> 6);
    int q = tid & 63;
    int b = token >> 11;
    int i1 = d_idx1[token], i2 = d_idx2[token];
    float w1 = d_g1[token], w2 = d_g2[token];
    float4 xv = ((const float4*)x)[(size_t)token*64 + q];
    float4 ga = ((const float4*)(d_gates + (i1*BB + b)*DD))[q];
    float4 gb = ((const float4*)(d_gates + (i2*BB + b)*DD))[q];
    float4 o;
    o.x = xv.x * (w1*ga.x + w2*gb.x);
    o.y = xv.y * (w1*ga.y + w2*gb.y);
    o.z = xv.z * (w1*ga.z + w2*gb.z);
    o.w = xv.w * (w1*ga.w + w2*gb.w);
    ((float4*)out)[(size_t)token*64 + q] = o;

    if (blockIdx.x == 0) {
        if (tid < 128) {
            red[tid] = d_probsum[tid] * (float)d_count1[tid];
            d_probsum[tid] = 0.f;          // reset for next (deterministic) run
            d_count1[tid] = 0;
        }
        __syncthreads();
        if (tid < 64) red[tid] += red[tid + 64];
        __syncthreads();
        if (tid < 32) {
            float v = red[tid] + red[tid + 32];
#pragma unroll
            for (int off = 16; off > 0; off >>= 1)
                v += __shfl_xor_sync(0xffffffffu, v, off);
            if (tid == 0 && out_size > NTOK*DD) {
                float coef = (float)(EE*EE) * 0.01f / ((float)NN * (float)NN * (float)(BB*EE));
                out[NTOK*DD] = v * coef;
            }
        }
    }
}

// ------------------------- launch -------------------------
extern "C" void kernel_launch(void* const* d_in, const int* in_sizes, int n_in,
                              void* d_out, int out_size) {
    const float* x     = (const float*)d_in[0];
    const float* audio = (const float*)d_in[1];
    const float* wg    = (const float*)d_in[2];
    const float* Wq    = (const float*)d_in[3];
    const float* Wkv   = (const float*)d_in[4];
    const float* Wp    = (const float*)d_in[5];
    const float* bp    = (const float*)d_in[6];
    float* out = (float*)d_out;

    k_gating<<<NTOK/8, 256>>>(x, wg);
    k_qU<<<EB, 1024>>>(audio, Wq, Wkv);
    k_poslogy<<<EB*NG, 256>>>(x, Wkv, Wp);
    k_og<<<EB, 1024>>>(Wkv, Wp, bp);
    k_combine<<<NTOK/4, 256>>>(x, out, out_size);
}

// round 14
// speedup vs baseline: 1.1875x; 1.0771x over previous
#include <cuda_runtime.h>
#include <math.h>

#define BB   8
#define NN   2048
#define DD   256
#define EE   16
#define HH   8
#define CAPC 256
#define NTOK (BB*NN)
#define EB   128
#define NG   8          // slot-groups per (e,b): 32 slots each

// ------------------------- device scratch (no allocs; zero-initialized) ----------
__device__ int   d_idx1[NTOK];
__device__ int   d_idx2[NTOK];
__device__ float d_g1[NTOK];
__device__ float d_g2[NTOK];
__device__ float d_probsum[BB*EE];      // zeroed at load; re-zeroed each run in k_combine
__device__ int   d_count1[BB*EE];
__device__ float d_U[EB*HH*DD];         // per-(e,b) q projected through Wkv_k
__device__ float d_py[EB*NG*HH*DD];     // per-group unnormalized partial y
__device__ float d_pm[EB*NG*HH];        // per-group softmax max
__device__ float d_ps[EB*NG*HH];        // per-group softmax sum
__device__ float d_gates[EB*DD];

__device__ __forceinline__ void l2_prefetch(const float* p) {
    asm volatile("prefetch.global.L2 [%0];" :: "l"(p));
}

// ===== K1: blocks 0..127 = qU (FIRST, so they overlap the gating waves);
//           blocks 128..2175 = gating, warp per token =====
__global__ void __launch_bounds__(256) k_gate_qU(
    const float* __restrict__ x, const float* __restrict__ wg,
    const float* __restrict__ audio, const float* __restrict__ Wq,
    const float* __restrict__ Wkv)
{
    __shared__ float swgT[EE*260];
    __shared__ float sprob[EE];
    __shared__ int   scnt[EE];
    __shared__ float sa[DD];
    __shared__ float sq[DD];

    int tid = threadIdx.x, lane = tid & 31, warp = tid >> 5;

    if (blockIdx.x < EB) {
        // ---------------- qU for eb = blockIdx.x (runs in wave 1) ----------------
        int eb = blockIdx.x;
        int e = eb >> 3, b = eb & 7;
        if (tid < DD) sa[tid] = audio[b*DD + tid];
        __syncthreads();

        const float* Wqe = Wq + (size_t)e*DD*DD;
        {
            float a0=0.f, a1=0.f, a2=0.f, a3=0.f;
            for (int d = 0; d < DD; d += 4) {
                a0 += sa[d  ] * Wqe[(d  )*DD + tid];
                a1 += sa[d+1] * Wqe[(d+1)*DD + tid];
                a2 += sa[d+2] * Wqe[(d+2)*DD + tid];
                a3 += sa[d+3] * Wqe[(d+3)*DD + tid];
            }
            sq[tid] = a0 + a1 + a2 + a3;
        }
        __syncthreads();

        const float* Wkve = Wkv + (size_t)e*DD*2*DD;
        {
            int h = warp;                       // warp = head
            float qv = sq[h*32 + lane];
            float* Urow = d_U + ((size_t)eb*HH + h)*DD;
            for (int d = 0; d < DD; d += 4) {
                float v0 = Wkve[(size_t)(d  )*512 + h*32 + lane] * qv;
                float v1 = Wkve[(size_t)(d+1)*512 + h*32 + lane] * qv;
                float v2 = Wkve[(size_t)(d+2)*512 + h*32 + lane] * qv;
                float v3 = Wkve[(size_t)(d+3)*512 + h*32 + lane] * qv;
#pragma unroll
                for (int off = 16; off > 0; off >>= 1) {
                    v0 += __shfl_xor_sync(0xffffffffu, v0, off);
                    v1 += __shfl_xor_sync(0xffffffffu, v1, off);
                    v2 += __shfl_xor_sync(0xffffffffu, v2, off);
                    v3 += __shfl_xor_sync(0xffffffffu, v3, off);
                }
                if (lane == 0) { Urow[d]=v0; Urow[d+1]=v1; Urow[d+2]=v2; Urow[d+3]=v3; }
            }
        }
        return;
    }

    // ---------------- gating for tokens of block (blockIdx.x - EB) ----------------
    int blk = blockIdx.x - EB;
    if (tid < EE) { sprob[tid] = 0.f; scnt[tid] = 0; }
    for (int i = tid; i < DD*EE; i += 256)
        swgT[(i & 15)*260 + (i >> 4)] = wg[i];
    __syncthreads();

    int token = blk * 8 + warp;             // 8 tokens/block, same b
    const float4* xr4 = (const float4*)(x + (size_t)token * DD);
    float4 xa = xr4[lane], xb = xr4[lane + 32];

    float p[EE];
#pragma unroll
    for (int e = 0; e < EE; e++) {
        const float4* w4 = (const float4*)(swgT + e*260);
        float4 wa = w4[lane], wb = w4[lane + 32];
        p[e] = xa.x*wa.x + xa.y*wa.y + xa.z*wa.z + xa.w*wa.w
             + xb.x*wb.x + xb.y*wb.y + xb.z*wb.z + xb.w*wb.w;
    }
#pragma unroll
    for (int e = 0; e < EE; e++) {
#pragma unroll
        for (int off = 16; off > 0; off >>= 1)
            p[e] += __shfl_xor_sync(0xffffffffu, p[e], off);
    }
    float mx = p[0];
#pragma unroll
    for (int e = 1; e < EE; e++) mx = fmaxf(mx, p[e]);
    float s = 0.f;
#pragma unroll
    for (int e = 0; e < EE; e++) { p[e] = expf(p[e] - mx); s += p[e]; }
    float inv = 1.f / s;
#pragma unroll
    for (int e = 0; e < EE; e++) p[e] *= inv;
    int i1 = 0; float g1v = p[0];
#pragma unroll
    for (int e = 1; e < EE; e++) if (p[e] > g1v) { g1v = p[e]; i1 = e; }
    int i2 = (i1 == 0) ? 1 : 0; float g2v = p[i2];
#pragma unroll
    for (int e = 0; e < EE; e++)
        if (e != i1 && p[e] > g2v) { g2v = p[e]; i2 = e; }
    float denom = g1v + g2v + 1e-9f;

    if (lane == 0) {
        d_idx1[token] = i1; d_idx2[token] = i2;
        d_g1[token] = g1v / denom; d_g2[token] = g2v / denom;
        atomicAdd(&scnt[i1], 1);
    }
    if (lane < EE) atomicAdd(&sprob[lane], p[lane]);
    __syncthreads();
    if (tid < EE) {
        int b = (blk * 8) >> 11;
        atomicAdd(&d_probsum[b*EE + tid], sprob[tid]);
        atomicAdd(&d_count1[b*EE + tid], scnt[tid]);
    }
}

// ==== K2: scan + logits + online-softmax partial + partial y + weight prefetch ====
__global__ void __launch_bounds__(256) k_poslogy(
    const float* __restrict__ x, const float* __restrict__ Wkv,
    const float* __restrict__ Wp)
{
    __shared__ float sU[HH][DD];
    __shared__ int   s_slots[CAPC];
    __shared__ float sE[HH][32];
    __shared__ float smx[HH], ssm[HH];
    __shared__ int   swc1[8], swc2[8];
    __shared__ int   sbase1[8], sbase2[8];

    int ebg = blockIdx.x;
    int eb = ebg >> 3, grp = ebg & 7;       // 8 groups of 32 slots
    int e = eb >> 3, b = eb & 7;
    int tid = threadIdx.x, lane = tid & 31, warp = tid >> 5;

    if (tid < CAPC) s_slots[tid] = -1;
#pragma unroll
    for (int k = 0; k < 8; k++)
        ((float*)sU)[k*256 + tid] = d_U[(size_t)eb*2048 + k*256 + tid];

    // ---- L2 prefetch of og's cold weights: this block's (e,grp) share ----
    {
        const float* Wkve = Wkv + (size_t)e*DD*2*DD;
        const float* Wpe  = Wp  + (size_t)e*DD*DD;
        if (tid < 128) {                       // Wkv_v: 32 rows x 4 lines
            int r = tid >> 2, l = tid & 3;
            l2_prefetch(Wkve + (size_t)(grp*32 + r)*512 + 256 + l*32);
        }
        {                                      // Wp: 32 rows x 8 lines
            int r = tid >> 3, l = tid & 7;
            l2_prefetch(Wpe + (size_t)(grp*32 + r)*256 + l*32);
        }
    }

    // ---- ballot-based capacity scan (full, redundant per group) ----
    unsigned m1[8], m2[8];
    {
        int wc1 = 0, wc2 = 0;
#pragma unroll
        for (int r = 0; r < 8; r++) {
            int t = warp*256 + r*32 + lane;
            int v1 = d_idx1[b*NN + t];
            int v2 = d_idx2[b*NN + t];
            m1[r] = __ballot_sync(0xffffffffu, v1 == e);
            m2[r] = __ballot_sync(0xffffffffu, v2 == e);
            wc1 += __popc(m1[r]); wc2 += __popc(m2[r]);
        }
        if (lane == 0) { swc1[warp] = wc1; swc2[warp] = wc2; }
    }
    __syncthreads();
    if (tid == 0) {
        int run = 0;
        for (int w = 0; w < 8; w++) { sbase1[w] = run; run += swc1[w]; }
        int base2 = (run < CAPC) ? run : CAPC;     // m1_count capped
        for (int w = 0; w < 8; w++) { sbase2[w] = base2; base2 += swc2[w]; }
    }
    __syncthreads();
    {
        unsigned ltmask = (1u << lane) - 1u;
        int run = sbase1[warp];
#pragma unroll
        for (int r = 0; r < 8; r++) {
            unsigned m = m1[r];
            if (m & (1u << lane)) {
                int slot = run + __popc(m & ltmask);
                int t = warp*256 + r*32 + lane;
                if (slot < CAPC) s_slots[slot] = t;
                else if (grp == 0) d_g1[b*NN + t] = 0.f;
            }
            run += __popc(m);
        }
        run = sbase2[warp];
#pragma unroll
        for (int r = 0; r < 8; r++) {
            unsigned m = m2[r];
            if (m & (1u << lane)) {
                int slot = run + __popc(m & ltmask);
                int t = warp*256 + r*32 + lane;
                if (slot < CAPC) s_slots[slot] = t;
                else if (grp == 0) d_g2[b*NN + t] = 0.f;
            }
            run += __popc(m);
        }
    }
    __syncthreads();

    // ---- logits for this group's 32 slots (warp handles 4) ----
    const float scale = 0.17677669529663687f;    // 32^-0.5
#pragma unroll
    for (int ci = 0; ci < 4; ci++) {
        int sl = warp*4 + ci;                    // 0..31 within group
        int tok = s_slots[grp*32 + sl];
        float part[HH];
        if (tok >= 0) {
            const float4* xr4 = (const float4*)(x + ((size_t)b*NN + tok)*DD);
            float4 xa = xr4[lane], xb = xr4[lane + 32];
#pragma unroll
            for (int h = 0; h < HH; h++) {
                const float4* u4 = (const float4*)(&sU[h][0]);
                float4 ua = u4[lane], ub = u4[lane + 32];
                part[h] = xa.x*ua.x + xa.y*ua.y + xa.z*ua.z + xa.w*ua.w
                        + xb.x*ub.x + xb.y*ub.y + xb.z*ub.z + xb.w*ub.w;
            }
        } else {
#pragma unroll
            for (int h = 0; h < HH; h++) part[h] = 0.f;
        }
#pragma unroll
        for (int h = 0; h < HH; h++) {
            float v = part[h];
#pragma unroll
            for (int off = 16; off > 0; off >>= 1)
                v += __shfl_xor_sync(0xffffffffu, v, off);
            if (lane == 0) sE[h][sl] = (tok >= 0) ? v * scale : 0.f;
        }
    }
    __syncthreads();

    // ---- group-local online-softmax partial (warp h over 32 logits) ----
    if (warp < HH) {
        float v = sE[warp][lane];
        float mx = v;
#pragma unroll
        for (int off = 16; off > 0; off >>= 1)
            mx = fmaxf(mx, __shfl_xor_sync(0xffffffffu, mx, off));
        float ev = expf(v - mx);
        float s = ev;
#pragma unroll
        for (int off = 16; off > 0; off >>= 1)
            s += __shfl_xor_sync(0xffffffffu, s, off);
        sE[warp][lane] = ev;
        if (lane == 0) { smx[warp] = mx; ssm[warp] = s; }
    }
    __syncthreads();

    // ---- unnormalized partial y over own 32 slots (thread = d), MLP-4, x L1-hot ----
    {
        float yv[HH];
#pragma unroll
        for (int h = 0; h < HH; h++) yv[h] = 0.f;
#pragma unroll
        for (int c4 = 0; c4 < 8; c4++) {
            int t0 = s_slots[grp*32 + c4*4+0], t1 = s_slots[grp*32 + c4*4+1];
            int t2 = s_slots[grp*32 + c4*4+2], t3 = s_slots[grp*32 + c4*4+3];
            float x0 = (t0 >= 0) ? x[((size_t)b*NN + t0)*DD + tid] : 0.f;
            float x1 = (t1 >= 0) ? x[((size_t)b*NN + t1)*DD + tid] : 0.f;
            float x2 = (t2 >= 0) ? x[((size_t)b*NN + t2)*DD + tid] : 0.f;
            float x3 = (t3 >= 0) ? x[((size_t)b*NN + t3)*DD + tid] : 0.f;
#pragma unroll
            for (int h = 0; h < HH; h++) {
                yv[h] += sE[h][c4*4+0] * x0 + sE[h][c4*4+1] * x1
                       + sE[h][c4*4+2] * x2 + sE[h][c4*4+3] * x3;
            }
        }
#pragma unroll
        for (int h = 0; h < HH; h++)
            d_py[((size_t)ebg*HH + h)*DD + tid] = yv[h];
        if (tid < HH) { d_pm[ebg*HH + tid] = smx[tid]; d_ps[ebg*HH + tid] = ssm[tid]; }
    }
}

// ==== K3: softmax-merge + o-projection + sigmoid gate; 1024 thr, MLP-4 matvecs ====
__global__ void __launch_bounds__(1024, 1) k_og(
    const float* __restrict__ Wkv, const float* __restrict__ Wp,
    const float* __restrict__ bp)
{
    __shared__ float sw[NG][HH];
    __shared__ float sY[HH][DD];
    __shared__ float sO[DD];
    __shared__ float sRed[4][DD];

    int eb = blockIdx.x;
    int e = eb >> 3;
    int tid = threadIdx.x;
    int g = tid >> 8, wtid = tid & 255;

    // merge weights per head: w[g][h] = exp(m_g - M) / S
    if (tid < HH) {
        float m[NG];
#pragma unroll
        for (int g2 = 0; g2 < NG; g2++) m[g2] = d_pm[(eb*NG + g2)*HH + tid];
        float M = m[0];
#pragma unroll
        for (int g2 = 1; g2 < NG; g2++) M = fmaxf(M, m[g2]);
        float S = 0.f;
        float w[NG];
#pragma unroll
        for (int g2 = 0; g2 < NG; g2++) {
            w[g2] = expf(m[g2] - M);
            S += w[g2] * d_ps[(eb*NG + g2)*HH + tid];
        }
        float invS = 1.f / S;
#pragma unroll
        for (int g2 = 0; g2 < NG; g2++) sw[g2][tid] = w[g2] * invS;
    }
    __syncthreads();

    // sY[h][d] = sum_g w[g][h] * py[g][h][d]   (1024 threads, 2 elems each, MLP-2)
    for (int i = tid; i < HH*DD; i += 1024) {
        int h = i >> 8;
        float a0 = 0.f, a1 = 0.f;
#pragma unroll
        for (int g2 = 0; g2 < NG; g2 += 2) {
            a0 += d_py[(size_t)(eb*NG + g2  )*2048 + i] * sw[g2  ][h];
            a1 += d_py[(size_t)(eb*NG + g2+1)*2048 + i] * sw[g2+1][h];
        }
        ((float*)sY)[i] = a0 + a1;
    }
    __syncthreads();

    // o[j] = sum_d y[h(j)][d] * Wkv_v[e][d][256+j]; 4-way split over d, MLP-4
    const float* Wkve = Wkv + (size_t)e*DD*2*DD;
    {
        int h = wtid >> 5;
        int d0 = g*64;
        float a0=0.f, a1=0.f, a2=0.f, a3=0.f;
#pragma unroll 4
        for (int d = d0; d < d0 + 64; d += 4) {
            a0 += sY[h][d  ] * Wkve[(size_t)(d  )*512 + 256 + wtid];
            a1 += sY[h][d+1] * Wkve[(size_t)(d+1)*512 + 256 + wtid];
            a2 += sY[h][d+2] * Wkve[(size_t)(d+2)*512 + 256 + wtid];
            a3 += sY[h][d+3] * Wkve[(size_t)(d+3)*512 + 256 + wtid];
        }
        sRed[g][wtid] = a0 + a1 + a2 + a3;
    }
    __syncthreads();
    if (tid < DD)
        sO[tid] = sRed[0][tid] + sRed[1][tid] + sRed[2][tid] + sRed[3][tid];
    __syncthreads();

    // gate[d] = sigmoid(sum_j o[j]*Wp[e][j][d] + bp[e][d]); 4-way split over j, MLP-4
    {
        const float* Wpe = Wp + (size_t)e*DD*DD;
        int j0 = g*64;
        float a0=0.f, a1=0.f, a2=0.f, a3=0.f;
#pragma unroll 4
        for (int j = j0; j < j0 + 64; j += 4) {
            a0 += sO[j  ] * Wpe[(j  )*DD + wtid];
            a1 += sO[j+1] * Wpe[(j+1)*DD + wtid];
            a2 += sO[j+2] * Wpe[(j+2)*DD + wtid];
            a3 += sO[j+3] * Wpe[(j+3)*DD + wtid];
        }
        sRed[g][wtid] = a0 + a1 + a2 + a3;
    }
    __syncthreads();
    if (tid < DD) {
        float gsum = sRed[0][tid] + sRed[1][tid] + sRed[2][tid] + sRed[3][tid]
                   + bp[e*DD + tid];
        d_gates[eb*DD + tid] = 1.f / (1.f + expf(-gsum));
    }
}

// ============ K4: combine + loss (block 0) + counter reset ============
__global__ void __launch_bounds__(256) k_combine(
    const float* __restrict__ x, float* __restrict__ out, int out_size)
{
    __shared__ float red[128];
    int tid = threadIdx.x;
    int token = blockIdx.x*4 + (tid >> 6);
    int q = tid & 63;
    int b = token >> 11;
    int i1 = d_idx1[token], i2 = d_idx2[token];
    float w1 = d_g1[token], w2 = d_g2[token];
    float4 xv = ((const float4*)x)[(size_t)token*64 + q];
    float4 ga = ((const float4*)(d_gates + (i1*BB + b)*DD))[q];
    float4 gb = ((const float4*)(d_gates + (i2*BB + b)*DD))[q];
    float4 o;
    o.x = xv.x * (w1*ga.x + w2*gb.x);
    o.y = xv.y * (w1*ga.y + w2*gb.y);
    o.z = xv.z * (w1*ga.z + w2*gb.z);
    o.w = xv.w * (w1*ga.w + w2*gb.w);
    ((float4*)out)[(size_t)token*64 + q] = o;

    if (blockIdx.x == 0) {
        if (tid < 128) {
            red[tid] = d_probsum[tid] * (float)d_count1[tid];
            d_probsum[tid] = 0.f;          // reset for next (deterministic) run
            d_count1[tid] = 0;
        }
        __syncthreads();
        if (tid < 64) red[tid] += red[tid + 64];
        __syncthreads();
        if (tid < 32) {
            float v = red[tid] + red[tid + 32];
#pragma unroll
            for (int off = 16; off > 0; off >>= 1)
                v += __shfl_xor_sync(0xffffffffu, v, off);
            if (tid == 0 && out_size > NTOK*DD) {
                float coef = (float)(EE*EE) * 0.01f / ((float)NN * (float)NN * (float)(BB*EE));
                out[NTOK*DD] = v * coef;
            }
        }
    }
}

// ------------------------- launch -------------------------
extern "C" void kernel_launch(void* const* d_in, const int* in_sizes, int n_in,
                              void* d_out, int out_size) {
    const float* x     = (const float*)d_in[0];
    const float* audio = (const float*)d_in[1];
    const float* wg    = (const float*)d_in[2];
    const float* Wq    = (const float*)d_in[3];
    const float* Wkv   = (const float*)d_in[4];
    const float* Wp    = (const float*)d_in[5];
    const float* bp    = (const float*)d_in[6];
    float* out = (float*)d_out;

    k_gate_qU<<<EB + NTOK/8, 256>>>(x, wg, audio, Wq, Wkv);
    k_poslogy<<<EB*NG, 256>>>(x, Wkv, Wp);
    k_og<<<EB, 1024>>>(Wkv, Wp, bp);
    k_combine<<<NTOK/4, 256>>>(x, out, out_size);
}